// round 15
// baseline (speedup 1.0000x reference)
#include <cuda_runtime.h>
#include <cuda_bf16.h>
#include <cstdint>

#define BB  2
#define SS  2048
#define DD  1024
#define HH  16
#define HDD 64
#define NT  (BB * SS)   // 4096 tokens

// ---------------- scratch (no allocation allowed) ----------------
__device__ __nv_bfloat16 g_hb[NT * DD];      // hidden, bf16
__device__ __nv_bfloat16 g_q[NT * DD];       // [B,H,S,HD] bf16
__device__ __nv_bfloat16 g_k[NT * DD];       // [B,H,S,HD] bf16
__device__ uint32_t      g_v[NT * DD / 2];   // [bh][s2][d] words: {V[2s2][d],V[2s2+1][d]}
__device__ __nv_bfloat16 g_ctx[NT * DD];     // [token, D] bf16
__device__ float         g_x[NT * DD];       // proj + residual, fp32
__device__ uint32_t      g_wq[DD * DD / 2];  // packed [n][k2]: {W[2k2][n],W[2k2+1][n]}
__device__ uint32_t      g_wk[DD * DD / 2];
__device__ uint32_t      g_wv[DD * DD / 2];
__device__ uint32_t      g_wo[DD * DD / 2];

// ---------------- helpers ----------------
__device__ __forceinline__ uint32_t pack_bf16(float a, float b) {
    __nv_bfloat162 t = __floats2bfloat162_rn(a, b);
    return *reinterpret_cast<uint32_t*>(&t);
}
// {lo = exp2(lo_in), hi = exp2(hi_in)} in bf16x2, single MUFU op
__device__ __forceinline__ uint32_t exp2_bf16x2(float hi, float lo) {
    uint32_t p, d;
    asm("cvt.rn.bf16x2.f32 %0, %1, %2;" : "=r"(p) : "f"(hi), "f"(lo));
    asm("ex2.approx.ftz.bf16x2 %0, %1;" : "=r"(d) : "r"(p));
    return d;
}
__device__ __forceinline__ void mma_bf16(float* c, const uint32_t* a, const uint32_t* b) {
    asm volatile(
        "mma.sync.aligned.m16n8k16.row.col.f32.bf16.bf16.f32 "
        "{%0,%1,%2,%3},{%4,%5,%6,%7},{%8,%9},{%0,%1,%2,%3};\n"
        : "+f"(c[0]), "+f"(c[1]), "+f"(c[2]), "+f"(c[3])
        : "r"(a[0]), "r"(a[1]), "r"(a[2]), "r"(a[3]), "r"(b[0]), "r"(b[1]));
}
__device__ __forceinline__ uint32_t smem_u32(const void* p) {
    return (uint32_t)__cvta_generic_to_shared(p);
}
__device__ __forceinline__ void cpa16(uint32_t s, const void* g) {
    asm volatile("cp.async.cg.shared.global [%0], [%1], 16;" :: "r"(s), "l"(g));
}
#define CP_COMMIT asm volatile("cp.async.commit_group;")
#define CP_WAIT2  asm volatile("cp.async.wait_group 2;")
#define CP_WAIT1  asm volatile("cp.async.wait_group 1;")
#define CP_WAIT0  asm volatile("cp.async.wait_group 0;")
#define LDSM_X4(r0, r1, r2, r3, addr) \
    asm volatile("ldmatrix.sync.aligned.m8n8.x4.shared.b16 {%0,%1,%2,%3}, [%4];" \
                 : "=r"(r0), "=r"(r1), "=r"(r2), "=r"(r3) : "r"(addr))

// ---------------- conversion kernels ----------------
__global__ void __launch_bounds__(256) conv_h(const float* __restrict__ in,
                                              __nv_bfloat16* __restrict__ out)
{
    int i = (blockIdx.x * 256 + threadIdx.x) * 4;
    float4 v = *(const float4*)(in + i);
    uint2 w;
    w.x = pack_bf16(v.x, v.y);
    w.y = pack_bf16(v.z, v.w);
    *(uint2*)(out + i) = w;
}

// pack weights into [n][k2] via smem transpose. block = one 32k2 x 32n tile.
__global__ void __launch_bounds__(256) pack_all(const float* __restrict__ Wq,
                                                const float* __restrict__ Wk,
                                                const float* __restrict__ Wv,
                                                const float* __restrict__ Wo)
{
    __shared__ uint32_t tile[32][33];
    const int bx = blockIdx.x;                 // 4 * 16 * 32 = 2048 blocks
    const int sect = bx >> 9;
    const int rem = bx & 511;
    const int k2b = (rem >> 5) * 32, nb = (rem & 31) * 32;
    const float* W = (sect == 0) ? Wq : (sect == 1) ? Wk : (sect == 2) ? Wv : Wo;
    uint32_t* Wp = (sect == 0) ? g_wq : (sect == 1) ? g_wk : (sect == 2) ? g_wv : g_wo;
    const int tid = threadIdx.x;

    {
        const int k2l = tid >> 3, nl4 = (tid & 7) * 4;
        float4 r0 = *(const float4*)(W + (size_t)(2 * (k2b + k2l)) * DD + nb + nl4);
        float4 r1 = *(const float4*)(W + (size_t)(2 * (k2b + k2l) + 1) * DD + nb + nl4);
        tile[k2l][nl4 + 0] = pack_bf16(r0.x, r1.x);
        tile[k2l][nl4 + 1] = pack_bf16(r0.y, r1.y);
        tile[k2l][nl4 + 2] = pack_bf16(r0.z, r1.z);
        tile[k2l][nl4 + 3] = pack_bf16(r0.w, r1.w);
    }
    __syncthreads();
    {
        const int nl = tid >> 3, k2l4 = (tid & 7) * 4;
        uint4 w;
        w.x = tile[k2l4 + 0][nl];
        w.y = tile[k2l4 + 1][nl];
        w.z = tile[k2l4 + 2][nl];
        w.w = tile[k2l4 + 3][nl];
        *(uint4*)(Wp + (size_t)(nb + nl) * (DD / 2) + k2b + k2l4) = w;
    }
}

// =================================================================
// BF16 tensor-core GEMM. 128x128x32 tiles, 256 thr (8 warps 2x4),
// warp tile 64x32, mma.m16n8k16. 3-stage cp.async pipeline, ONE
// barrier per k-tile. A and B fragments both via ldmatrix.x4.
// B smem: [n=128 rows][16 k2 words], 80 B pitch (16B-aligned rows).
// mode 3: fused QKV (z: 0 Q, 1 K scatter; 2 V s-pair-packed scatter)
// mode 1: fp32 out = acc + bias + resid (O projection)
// =================================================================
#define ABUF (128 * 144)     // 18432 B per A buffer
#define BPITCH 80            // B smem row pitch in bytes (multiple of 16)
#define BBUF (128 * BPITCH)  // 10240 B per B buffer
#define BS_OFF (3 * ABUF)    // 55296
#define GEMM_SMEM (3 * ABUF + 3 * BBUF)   // 86016 B

__global__ void __launch_bounds__(256) gemm_bf16(
    const __nv_bfloat16* __restrict__ A,
    const uint32_t* __restrict__ Wp1,
    const float* __restrict__ bias1,
    const float* __restrict__ bq, const float* __restrict__ bk,
    const float* __restrict__ bv,
    const float* __restrict__ resid,
    float* __restrict__ out, int mode)
{
    extern __shared__ char smraw[];
    const uint32_t sbase = smem_u32(smraw);

    const int tid  = threadIdx.x;
    const int warp = tid >> 5, lane = tid & 31;
    const int g = lane >> 2, c = lane & 3;
    const int wm = (warp >> 2) * 64, wn = (warp & 3) * 32;
    const int row0 = blockIdx.y * 128, col0 = blockIdx.x * 128;

    const uint32_t* Wp;
    const float* bias;
    int zmode;   // 0: Q/K scatter, 2: V packed scatter, 1: O-proj
    if (mode == 3) {
        const int z = blockIdx.z;
        Wp   = (z == 0) ? g_wq : (z == 1) ? g_wk : g_wv;
        bias = (z == 0) ? bq : (z == 1) ? bk : bv;
        zmode = (z < 2) ? 0 : 2;
    } else {
        Wp = Wp1; bias = bias1; zmode = 1;
    }

    const uint32_t off_a = (uint32_t)((lane & 15) * 144 + (lane >> 4) * 16);
    const uint32_t off_b = (uint32_t)((((lane & 7) + ((lane >> 4) & 1) * 8)) * BPITCH
                                      + ((lane >> 3) & 1) * 16);

    float acc[4][4][4];
#pragma unroll
    for (int mi = 0; mi < 4; mi++)
#pragma unroll
        for (int ni = 0; ni < 4; ni++)
#pragma unroll
            for (int r = 0; r < 4; r++) acc[mi][ni][r] = 0.f;

#define LOAD_TILE(t, buf)                                                      \
    {                                                                          \
        const int _t = (t), _b = (buf);                                        \
        _Pragma("unroll")                                                      \
        for (int i = 0; i < 2; i++) {                                          \
            int idx = tid + 256 * i;                                           \
            int r = idx >> 2, kc = (idx & 3) * 8;                              \
            cpa16(sbase + _b * ABUF + r * 144 + kc * 2,                        \
                  A + (size_t)(row0 + r) * DD + _t * 32 + kc);                 \
        }                                                                      \
        _Pragma("unroll")                                                      \
        for (int i = 0; i < 2; i++) {                                          \
            int idx = tid + 256 * i;                                           \
            int r = idx >> 2, ch = idx & 3;                                    \
            cpa16(sbase + BS_OFF + _b * BBUF + r * BPITCH + ch * 16,           \
                  Wp + (size_t)(col0 + r) * (DD / 2) + _t * 16 + ch * 4);      \
        }                                                                      \
    }

    LOAD_TILE(0, 0); CP_COMMIT;
    LOAD_TILE(1, 1); CP_COMMIT;

    const int NTL = DD / 32;   // 32 k-tiles
    int buf = 0;
    for (int t = 0; t < NTL; t++) {
        if (t < NTL - 1) { CP_WAIT1; } else { CP_WAIT0; }
        __syncthreads();
        if (t + 2 < NTL) {
            int nb = buf + 2; if (nb >= 3) nb -= 3;
            LOAD_TILE(t + 2, nb); CP_COMMIT;
        }

        const uint32_t Au = sbase + buf * ABUF + wm * 144 + off_a;
        const uint32_t Bu = sbase + BS_OFF + buf * BBUF + wn * BPITCH + off_b;
#pragma unroll
        for (int s = 0; s < 2; s++) {
            uint32_t afr[4][4], bfr[2][4];
#pragma unroll
            for (int mi = 0; mi < 4; mi++)
                LDSM_X4(afr[mi][0], afr[mi][1], afr[mi][2], afr[mi][3],
                        Au + mi * 2304 + s * 32);
#pragma unroll
            for (int nig = 0; nig < 2; nig++)
                LDSM_X4(bfr[nig][0], bfr[nig][1], bfr[nig][2], bfr[nig][3],
                        Bu + nig * (16 * BPITCH) + s * 32);
#pragma unroll
            for (int mi = 0; mi < 4; mi++)
#pragma unroll
                for (int nig = 0; nig < 2; nig++) {
                    mma_bf16(acc[mi][2 * nig],     afr[mi], &bfr[nig][0]);
                    mma_bf16(acc[mi][2 * nig + 1], afr[mi], &bfr[nig][2]);
                }
        }
        if (++buf >= 3) buf = 0;
    }
#undef LOAD_TILE

    // ---- epilogue ----
#pragma unroll
    for (int mi = 0; mi < 4; mi++) {
#pragma unroll
        for (int ni = 0; ni < 4; ni++) {
            const int col = col0 + wn + ni * 8 + 2 * c;
            const float b0 = bias[col], b1 = bias[col + 1];
            const int r1 = row0 + wm + mi * 16 + g;
            const int r2 = r1 + 8;
            const float v0 = acc[mi][ni][0] + b0, v1 = acc[mi][ni][1] + b1;
            const float v2 = acc[mi][ni][2] + b0, v3 = acc[mi][ni][3] + b1;
            if (zmode == 0) {
                __nv_bfloat16* ob = (blockIdx.z == 0) ? g_q : g_k;
                const int bb1 = r1 >> 11, s1 = r1 & 2047;
                const int bb2 = r2 >> 11, s2 = r2 & 2047;
                const int h = col >> 6, d = col & 63;
                *(uint32_t*)(ob + (((size_t)(bb1 * HH + h)) * SS + s1) * HDD + d) = pack_bf16(v0, v1);
                *(uint32_t*)(ob + (((size_t)(bb2 * HH + h)) * SS + s2) * HDD + d) = pack_bf16(v2, v3);
            } else if (zmode == 2) {
                // V packed scatter: word g_v[(bh*(SS/2)+s2)*HDD + d] = {V[2s2][d], V[2s2+1][d]}
                __nv_bfloat16* ov = (__nv_bfloat16*)g_v;
                const int bb1 = r1 >> 11, s1 = r1 & 2047;
                const int bb2 = r2 >> 11, s2 = r2 & 2047;
                const int h = (col & 1023) >> 6, d = col & 63;
                ov[(((size_t)(bb1 * HH + h) * (SS / 2) + (s1 >> 1)) * HDD + d)     * 2 + (s1 & 1)] = __float2bfloat16(v0);
                ov[(((size_t)(bb1 * HH + h) * (SS / 2) + (s1 >> 1)) * HDD + d + 1) * 2 + (s1 & 1)] = __float2bfloat16(v1);
                ov[(((size_t)(bb2 * HH + h) * (SS / 2) + (s2 >> 1)) * HDD + d)     * 2 + (s2 & 1)] = __float2bfloat16(v2);
                ov[(((size_t)(bb2 * HH + h) * (SS / 2) + (s2 >> 1)) * HDD + d + 1) * 2 + (s2 & 1)] = __float2bfloat16(v3);
            } else {
                const float2 rr1 = *(const float2*)(resid + (size_t)r1 * DD + col);
                const float2 rr2 = *(const float2*)(resid + (size_t)r2 * DD + col);
                *(float2*)(out + (size_t)r1 * DD + col) = make_float2(v0 + rr1.x, v1 + rr1.y);
                *(float2*)(out + (size_t)r2 * DD + col) = make_float2(v2 + rr2.x, v3 + rr2.y);
            }
        }
    }
}

// =================================================================
// Flash attention, bf16 m16n8k16, max-free softmax via ex2.bf16x2,
// l accumulated by ones-MMA. 3-stage K/V/mask pipeline, one barrier
// per tile. Q aliased into K buffer 2. K and V fragments via scalar
// word loads (R11 form — measured faster than ldmatrix here).
// Block = 64 q-rows of one (b,h), 128 thr (4 warps x 16 rows).
// =================================================================
#define QPW 36     // K word pitch (144 B rows)
#define VPW 72     // V word pitch (288 B rows)
#define KBUF (64 * QPW)       // 2304 words per K buffer
#define VBUF (32 * VPW)       // 2304 words per V buffer
#define K2E 0.1803368824f     // 0.125 * log2(e)
#define L2E 1.4426950409f
#define ONES2 0x3F803F80u     // bf16 {1.0, 1.0}
#define FLASH_SMEM ((3 * KBUF + 3 * VBUF) * 4 + 3 * 64 * 4)   // 56064 B

__global__ void __launch_bounds__(128) flash_bf16(const float* __restrict__ mask)
{
    extern __shared__ char smraw[];
    uint32_t* Ks = (uint32_t*)smraw;            // [3][64][QPW]
    uint32_t* Qs = Ks + 2 * KBUF;               // alias: K buffer 2
    uint32_t* Vs = Ks + 3 * KBUF;               // [3][32][VPW]
    float*    Ms = (float*)(Vs + 3 * VBUF);     // [3][64]

    const int tid  = threadIdx.x;
    const int warp = tid >> 5, lane = tid & 31;
    const int g = lane >> 2, c = lane & 3;
    const int wr = warp * 16;

    const int bh = blockIdx.y;
    const int b = bh >> 4;
    const int q0 = blockIdx.x * 64;

    const __nv_bfloat16* Qg = g_q + (size_t)bh * SS * HDD;
    const __nv_bfloat16* Kg = g_k + (size_t)bh * SS * HDD;
    const uint32_t*      Vg = g_v + (size_t)bh * (SS / 2) * HDD;
    const float* mrow = mask + (size_t)b * SS;

    // ---- prologue: Q into K-buf-2, then K/V tiles 0,1 ----
#pragma unroll
    for (int i = 0; i < 4; i++) {
        int idx = tid + 128 * i;
        int r = idx >> 3, kc = (idx & 7) * 8;
        cpa16(smem_u32((__nv_bfloat16*)Qs + r * 72 + kc),
              Qg + (size_t)(q0 + r) * HDD + kc);
    }
    CP_COMMIT;

#define LOAD_KV(k0v, bufv)                                                     \
    {                                                                          \
        const int _k0 = (k0v), _b = (bufv);                                    \
        _Pragma("unroll")                                                      \
        for (int i = 0; i < 4; i++) {                                          \
            int idx = tid + 128 * i;                                           \
            int r = idx >> 3, kc = (idx & 7) * 8;                              \
            cpa16(smem_u32((__nv_bfloat16*)(Ks + _b * KBUF) + r * 72 + kc),    \
                  Kg + (size_t)(_k0 + r) * HDD + kc);                          \
        }                                                                      \
        _Pragma("unroll")                                                      \
        for (int i = 0; i < 4; i++) {                                          \
            int idx = tid + 128 * i;                                           \
            int r = idx >> 4, cc = (idx & 15) * 4;                             \
            cpa16(smem_u32(Vs + _b * VBUF + r * VPW + cc),                     \
                  Vg + (size_t)(_k0 / 2 + r) * HDD + cc);                      \
        }                                                                      \
        if (tid < 16) cpa16(smem_u32(Ms + _b * 64 + tid * 4),                  \
                            mrow + _k0 + tid * 4);                             \
    }

    LOAD_KV(0, 0); CP_COMMIT;
    LOAD_KV(64, 1); CP_COMMIT;

    CP_WAIT2;           // Q group done
    __syncthreads();

    uint32_t qf[4][4];
#pragma unroll
    for (int ks = 0; ks < 4; ks++) {
        const int base = (wr + g) * QPW + ks * 8 + c;
        qf[ks][0] = Qs[base];
        qf[ks][1] = Qs[base + 8 * QPW];
        qf[ks][2] = Qs[base + 4];
        qf[ks][3] = Qs[base + 8 * QPW + 4];
    }
    __syncthreads();    // Q consumed; buf 2 free for kt=2 prefetch

    float l_acc[4] = {0.f, 0.f, 0.f, 0.f};
    const uint32_t ones[2] = {ONES2, ONES2};
    float o[8][4];
#pragma unroll
    for (int ni = 0; ni < 8; ni++)
#pragma unroll
        for (int r = 0; r < 4; r++) o[ni][r] = 0.f;

    const int NKT = SS / 64;
    int buf = 0;
    for (int kt = 0; kt < NKT; kt++) {
        if (kt < NKT - 1) { CP_WAIT1; } else { CP_WAIT0; }
        __syncthreads();
        if (kt + 2 < NKT) {
            int nb = buf + 2; if (nb >= 3) nb -= 3;
            LOAD_KV((kt + 2) * 64, nb); CP_COMMIT;
        }

        const uint32_t* Kb = Ks + buf * KBUF;
        const uint32_t* Vb = Vs + buf * VBUF;
        const float* Mb = Ms + buf * 64;

        // ---- S = Q K^T (scalar K word loads) ----
        float s[8][4];
#pragma unroll
        for (int ni = 0; ni < 8; ni++)
#pragma unroll
            for (int r = 0; r < 4; r++) s[ni][r] = 0.f;

#pragma unroll
        for (int ks = 0; ks < 4; ks++) {
#pragma unroll
            for (int ni = 0; ni < 8; ni++) {
                uint32_t bfr[2];
                const int base = (ni * 8 + g) * QPW + ks * 8 + c;
                bfr[0] = Kb[base];
                bfr[1] = Kb[base + 4];
                mma_bf16(s[ni], qf[ks], bfr);
            }
        }

        // ---- t = s*K2E + mask*L2E (exp2 domain, no max) ----
#pragma unroll
        for (int ni = 0; ni < 8; ni++) {
            const int col = ni * 8 + 2 * c;
            const float mk0 = Mb[col] * L2E, mk1 = Mb[col + 1] * L2E;
            s[ni][0] = fmaf(s[ni][0], K2E, mk0);
            s[ni][1] = fmaf(s[ni][1], K2E, mk1);
            s[ni][2] = fmaf(s[ni][2], K2E, mk0);
            s[ni][3] = fmaf(s[ni][3], K2E, mk1);
        }

        // ---- O += P V ; l += P*1  (P via ex2.bf16x2, in regs) ----
#pragma unroll
        for (int ks = 0; ks < 4; ks++) {
            uint32_t pf[4];
            pf[0] = exp2_bf16x2(s[2 * ks][1],     s[2 * ks][0]);
            pf[1] = exp2_bf16x2(s[2 * ks][3],     s[2 * ks][2]);
            pf[2] = exp2_bf16x2(s[2 * ks + 1][1], s[2 * ks + 1][0]);
            pf[3] = exp2_bf16x2(s[2 * ks + 1][3], s[2 * ks + 1][2]);
            mma_bf16(l_acc, pf, ones);
#pragma unroll
            for (int ni = 0; ni < 8; ni++) {
                uint32_t bfr[2];
                const int vb = (ks * 8 + c) * VPW + ni * 8 + g;
                bfr[0] = Vb[vb];
                bfr[1] = Vb[vb + 4 * VPW];
                mma_bf16(o[ni], pf, bfr);
            }
        }
        if (++buf >= 3) buf = 0;
    }
#undef LOAD_KV

    // ---- normalize (l replicated across columns by ones-MMA) ----
    const float inv0 = 1.f / l_acc[0];
    const float inv1 = 1.f / l_acc[2];
    const int h = bh & 15;
    __nv_bfloat16* Cg = g_ctx + (size_t)(b * SS + q0) * DD + h * HDD;
#pragma unroll
    for (int ni = 0; ni < 8; ni++) {
        const int col = ni * 8 + 2 * c;
        *(uint32_t*)(Cg + (size_t)(wr + g) * DD + col)     = pack_bf16(o[ni][0] * inv0, o[ni][1] * inv0);
        *(uint32_t*)(Cg + (size_t)(wr + g + 8) * DD + col) = pack_bf16(o[ni][2] * inv1, o[ni][3] * inv1);
    }
}

// =================================================================
// LayerNorm
// =================================================================
__device__ __forceinline__ float blockSum(float v, float* red)
{
    const int lane = threadIdx.x & 31, wid = threadIdx.x >> 5;
#pragma unroll
    for (int o = 16; o > 0; o >>= 1) v += __shfl_xor_sync(0xffffffffu, v, o);
    if (lane == 0) red[wid] = v;
    __syncthreads();
    if (wid == 0) {
        float t = (lane < 8) ? red[lane] : 0.f;
#pragma unroll
        for (int o = 4; o > 0; o >>= 1) t += __shfl_xor_sync(0xffffffffu, t, o);
        if (lane == 0) red[0] = t;
    }
    __syncthreads();
    float r = red[0];
    __syncthreads();
    return r;
}

__global__ void __launch_bounds__(256) ln_kernel(
    const float* __restrict__ x, const float* __restrict__ gamma,
    const float* __restrict__ beta, float* __restrict__ out)
{
    __shared__ float red[8];
    const int row = blockIdx.x;
    const int t = threadIdx.x;

    float4 v = ((const float4*)(x + (size_t)row * DD))[t];
    float s = v.x + v.y + v.z + v.w;
    float mu = blockSum(s, red) * (1.0f / DD);

    float dx0 = v.x - mu, dx1 = v.y - mu, dx2 = v.z - mu, dx3 = v.w - mu;
    float sq = dx0 * dx0 + dx1 * dx1 + dx2 * dx2 + dx3 * dx3;
    float var = blockSum(sq, red) * (1.0f / DD);
    float inv = rsqrtf(var + 1e-12f);

    float4 g = ((const float4*)gamma)[t];
    float4 b = ((const float4*)beta)[t];
    float4 o;
    o.x = dx0 * inv * g.x + b.x;
    o.y = dx1 * inv * g.y + b.y;
    o.z = dx2 * inv * g.z + b.z;
    o.w = dx3 * inv * g.w + b.w;
    ((float4*)(out + (size_t)row * DD))[t] = o;
}

// =================================================================
extern "C" void kernel_launch(void* const* d_in, const int* in_sizes, int n_in,
                              void* d_out, int out_size)
{
    const float* hidden = (const float*)d_in[0];
    const float* mask   = (const float*)d_in[1];
    const float* Wq     = (const float*)d_in[2];
    const float* bq     = (const float*)d_in[3];
    const float* Wk     = (const float*)d_in[4];
    const float* bk     = (const float*)d_in[5];
    const float* Wv     = (const float*)d_in[6];
    const float* bv     = (const float*)d_in[7];
    const float* Wo     = (const float*)d_in[8];
    const float* bo     = (const float*)d_in[9];
    const float* gamma  = (const float*)d_in[10];
    const float* beta   = (const float*)d_in[11];
    float* out = (float*)d_out;

    __nv_bfloat16 *hb, *ctx;
    uint32_t *wo;
    float *x;
    cudaGetSymbolAddress((void**)&hb,  g_hb);
    cudaGetSymbolAddress((void**)&ctx, g_ctx);
    cudaGetSymbolAddress((void**)&x,   g_x);
    cudaGetSymbolAddress((void**)&wo,  g_wo);

    cudaFuncSetAttribute(gemm_bf16,
                         cudaFuncAttributeMaxDynamicSharedMemorySize, GEMM_SMEM);
    cudaFuncSetAttribute(flash_bf16,
                         cudaFuncAttributeMaxDynamicSharedMemorySize, FLASH_SMEM);

    // conversions
    conv_h<<<NT * DD / 4 / 256, 256>>>(hidden, hb);
    pack_all<<<2048, 256>>>(Wq, Wk, Wv, Wo);

    // fused QKV projections (z = 0:Q, 1:K, 2:V)
    gemm_bf16<<<dim3(DD / 128, NT / 128, 3), 256, GEMM_SMEM>>>(
        hb, nullptr, nullptr, bq, bk, bv, nullptr, nullptr, 3);

    flash_bf16<<<dim3(SS / 64, BB * HH), 128, FLASH_SMEM>>>(mask);

    gemm_bf16<<<dim3(DD / 128, NT / 128, 1), 256, GEMM_SMEM>>>(
        ctx, wo, bo, nullptr, nullptr, nullptr, hidden, x, 1);

    ln_kernel<<<NT, 256>>>(x, gamma, beta, out);
}

// round 16
// speedup vs baseline: 1.0651x; 1.0651x over previous
#include <cuda_runtime.h>
#include <cuda_bf16.h>
#include <cstdint>

#define BB  2
#define SS  2048
#define DD  1024
#define HH  16
#define HDD 64
#define NT  (BB * SS)   // 4096 tokens

// ---------------- scratch (no allocation allowed) ----------------
__device__ __nv_bfloat16 g_hb[NT * DD];      // hidden, bf16
__device__ __nv_bfloat16 g_q[NT * DD];       // [B,H,S,HD] bf16
__device__ __nv_bfloat16 g_k[NT * DD];       // [B,H,S,HD] bf16
__device__ uint32_t      g_v[NT * DD / 2];   // [bh][s2][d] words: {V[2s2][d],V[2s2+1][d]}
__device__ __nv_bfloat16 g_ctx[NT * DD];     // [token, D] bf16
__device__ float         g_x[NT * DD];       // proj + residual, fp32
__device__ uint32_t      g_wq[DD * DD / 2];  // packed [n][k2]: {W[2k2][n],W[2k2+1][n]}
__device__ uint32_t      g_wk[DD * DD / 2];
__device__ uint32_t      g_wv[DD * DD / 2];
__device__ uint32_t      g_wo[DD * DD / 2];

// ---------------- helpers ----------------
__device__ __forceinline__ uint32_t pack_bf16(float a, float b) {
    __nv_bfloat162 t = __floats2bfloat162_rn(a, b);
    return *reinterpret_cast<uint32_t*>(&t);
}
// {lo = exp2(lo_in), hi = exp2(hi_in)} in bf16x2, single MUFU op
__device__ __forceinline__ uint32_t exp2_bf16x2(float hi, float lo) {
    uint32_t p, d;
    asm("cvt.rn.bf16x2.f32 %0, %1, %2;" : "=r"(p) : "f"(hi), "f"(lo));
    asm("ex2.approx.ftz.bf16x2 %0, %1;" : "=r"(d) : "r"(p));
    return d;
}
__device__ __forceinline__ void mma_bf16(float* c, const uint32_t* a, const uint32_t* b) {
    asm volatile(
        "mma.sync.aligned.m16n8k16.row.col.f32.bf16.bf16.f32 "
        "{%0,%1,%2,%3},{%4,%5,%6,%7},{%8,%9},{%0,%1,%2,%3};\n"
        : "+f"(c[0]), "+f"(c[1]), "+f"(c[2]), "+f"(c[3])
        : "r"(a[0]), "r"(a[1]), "r"(a[2]), "r"(a[3]), "r"(b[0]), "r"(b[1]));
}
__device__ __forceinline__ uint32_t smem_u32(const void* p) {
    return (uint32_t)__cvta_generic_to_shared(p);
}
__device__ __forceinline__ void cpa16(uint32_t s, const void* g) {
    asm volatile("cp.async.cg.shared.global [%0], [%1], 16;" :: "r"(s), "l"(g));
}
#define CP_COMMIT asm volatile("cp.async.commit_group;")
#define CP_WAIT1  asm volatile("cp.async.wait_group 1;")
#define CP_WAIT0  asm volatile("cp.async.wait_group 0;")
#define LDSM_X4(r0, r1, r2, r3, addr) \
    asm volatile("ldmatrix.sync.aligned.m8n8.x4.shared.b16 {%0,%1,%2,%3}, [%4];" \
                 : "=r"(r0), "=r"(r1), "=r"(r2), "=r"(r3) : "r"(addr))

// ---------------- conversion kernels ----------------
__global__ void __launch_bounds__(256) conv_h(const float* __restrict__ in,
                                              __nv_bfloat16* __restrict__ out)
{
    int i = (blockIdx.x * 256 + threadIdx.x) * 4;
    float4 v = *(const float4*)(in + i);
    uint2 w;
    w.x = pack_bf16(v.x, v.y);
    w.y = pack_bf16(v.z, v.w);
    *(uint2*)(out + i) = w;
}

// pack weights into [n][k2] via smem transpose. block = one 32k2 x 32n tile.
__global__ void __launch_bounds__(256) pack_all(const float* __restrict__ Wq,
                                                const float* __restrict__ Wk,
                                                const float* __restrict__ Wv,
                                                const float* __restrict__ Wo)
{
    __shared__ uint32_t tile[32][33];
    const int bx = blockIdx.x;                 // 4 * 16 * 32 = 2048 blocks
    const int sect = bx >> 9;
    const int rem = bx & 511;
    const int k2b = (rem >> 5) * 32, nb = (rem & 31) * 32;
    const float* W = (sect == 0) ? Wq : (sect == 1) ? Wk : (sect == 2) ? Wv : Wo;
    uint32_t* Wp = (sect == 0) ? g_wq : (sect == 1) ? g_wk : (sect == 2) ? g_wv : g_wo;
    const int tid = threadIdx.x;

    {
        const int k2l = tid >> 3, nl4 = (tid & 7) * 4;
        float4 r0 = *(const float4*)(W + (size_t)(2 * (k2b + k2l)) * DD + nb + nl4);
        float4 r1 = *(const float4*)(W + (size_t)(2 * (k2b + k2l) + 1) * DD + nb + nl4);
        tile[k2l][nl4 + 0] = pack_bf16(r0.x, r1.x);
        tile[k2l][nl4 + 1] = pack_bf16(r0.y, r1.y);
        tile[k2l][nl4 + 2] = pack_bf16(r0.z, r1.z);
        tile[k2l][nl4 + 3] = pack_bf16(r0.w, r1.w);
    }
    __syncthreads();
    {
        const int nl = tid >> 3, k2l4 = (tid & 7) * 4;
        uint4 w;
        w.x = tile[k2l4 + 0][nl];
        w.y = tile[k2l4 + 1][nl];
        w.z = tile[k2l4 + 2][nl];
        w.w = tile[k2l4 + 3][nl];
        *(uint4*)(Wp + (size_t)(nb + nl) * (DD / 2) + k2b + k2l4) = w;
    }
}

// =================================================================
// BF16 tensor-core GEMM. 128x128x32 tiles, 256 thr (8 warps 2x4),
// warp tile 64x32, mma.m16n8k16. 2-stage cp.async pipeline (smaller
// smem -> 3 CTAs/SM). A and B fragments via ldmatrix.x4.
// B smem: [n=128 rows][16 k2 words], 80 B pitch.
// mode 3: fused QKV (z: 0 Q, 1 K scatter; 2 V s-pair-packed scatter)
// mode 1: fp32 out = acc + bias + resid (O projection)
// =================================================================
#define ABUF (128 * 144)     // 18432 B per A buffer
#define BPITCH 80            // B smem row pitch in bytes (multiple of 16)
#define BBUF (128 * BPITCH)  // 10240 B per B buffer
#define BS_OFF (2 * ABUF)    // 36864
#define GEMM_SMEM (2 * ABUF + 2 * BBUF)   // 57344 B -> 3 CTAs/SM

__global__ void __launch_bounds__(256) gemm_bf16(
    const __nv_bfloat16* __restrict__ A,
    const uint32_t* __restrict__ Wp1,
    const float* __restrict__ bias1,
    const float* __restrict__ bq, const float* __restrict__ bk,
    const float* __restrict__ bv,
    const float* __restrict__ resid,
    float* __restrict__ out, int mode)
{
    extern __shared__ char smraw[];
    const uint32_t sbase = smem_u32(smraw);

    const int tid  = threadIdx.x;
    const int warp = tid >> 5, lane = tid & 31;
    const int g = lane >> 2, c = lane & 3;
    const int wm = (warp >> 2) * 64, wn = (warp & 3) * 32;
    const int row0 = blockIdx.y * 128, col0 = blockIdx.x * 128;

    const uint32_t* Wp;
    const float* bias;
    int zmode;   // 0: Q/K scatter, 2: V packed scatter, 1: O-proj
    if (mode == 3) {
        const int z = blockIdx.z;
        Wp   = (z == 0) ? g_wq : (z == 1) ? g_wk : g_wv;
        bias = (z == 0) ? bq : (z == 1) ? bk : bv;
        zmode = (z < 2) ? 0 : 2;
    } else {
        Wp = Wp1; bias = bias1; zmode = 1;
    }

    const uint32_t off_a = (uint32_t)((lane & 15) * 144 + (lane >> 4) * 16);
    const uint32_t off_b = (uint32_t)((((lane & 7) + ((lane >> 4) & 1) * 8)) * BPITCH
                                      + ((lane >> 3) & 1) * 16);

    float acc[4][4][4];
#pragma unroll
    for (int mi = 0; mi < 4; mi++)
#pragma unroll
        for (int ni = 0; ni < 4; ni++)
#pragma unroll
            for (int r = 0; r < 4; r++) acc[mi][ni][r] = 0.f;

#define LOAD_TILE(t, buf)                                                      \
    {                                                                          \
        const int _t = (t), _b = (buf);                                        \
        _Pragma("unroll")                                                      \
        for (int i = 0; i < 2; i++) {                                          \
            int idx = tid + 256 * i;                                           \
            int r = idx >> 2, kc = (idx & 3) * 8;                              \
            cpa16(sbase + _b * ABUF + r * 144 + kc * 2,                        \
                  A + (size_t)(row0 + r) * DD + _t * 32 + kc);                 \
        }                                                                      \
        _Pragma("unroll")                                                      \
        for (int i = 0; i < 2; i++) {                                          \
            int idx = tid + 256 * i;                                           \
            int r = idx >> 2, ch = idx & 3;                                    \
            cpa16(sbase + BS_OFF + _b * BBUF + r * BPITCH + ch * 16,           \
                  Wp + (size_t)(col0 + r) * (DD / 2) + _t * 16 + ch * 4);      \
        }                                                                      \
    }

    LOAD_TILE(0, 0); CP_COMMIT;
    LOAD_TILE(1, 1); CP_COMMIT;

    const int NTL = DD / 32;   // 32 k-tiles
    for (int t = 0; t < NTL; t++) {
        const int buf = t & 1;
        if (t < NTL - 1) { CP_WAIT1; } else { CP_WAIT0; }
        __syncthreads();

        const uint32_t Au = sbase + buf * ABUF + wm * 144 + off_a;
        const uint32_t Bu = sbase + BS_OFF + buf * BBUF + wn * BPITCH + off_b;
#pragma unroll
        for (int s = 0; s < 2; s++) {
            uint32_t afr[4][4], bfr[2][4];
#pragma unroll
            for (int mi = 0; mi < 4; mi++)
                LDSM_X4(afr[mi][0], afr[mi][1], afr[mi][2], afr[mi][3],
                        Au + mi * 2304 + s * 32);
#pragma unroll
            for (int nig = 0; nig < 2; nig++)
                LDSM_X4(bfr[nig][0], bfr[nig][1], bfr[nig][2], bfr[nig][3],
                        Bu + nig * (16 * BPITCH) + s * 32);
#pragma unroll
            for (int mi = 0; mi < 4; mi++)
#pragma unroll
                for (int nig = 0; nig < 2; nig++) {
                    mma_bf16(acc[mi][2 * nig],     afr[mi], &bfr[nig][0]);
                    mma_bf16(acc[mi][2 * nig + 1], afr[mi], &bfr[nig][2]);
                }
        }
        __syncthreads();   // all warps done reading buf before refill
        if (t + 2 < NTL) { LOAD_TILE(t + 2, buf); CP_COMMIT; }
    }
#undef LOAD_TILE

    // ---- epilogue ----
#pragma unroll
    for (int mi = 0; mi < 4; mi++) {
#pragma unroll
        for (int ni = 0; ni < 4; ni++) {
            const int col = col0 + wn + ni * 8 + 2 * c;
            const float b0 = bias[col], b1 = bias[col + 1];
            const int r1 = row0 + wm + mi * 16 + g;
            const int r2 = r1 + 8;
            const float v0 = acc[mi][ni][0] + b0, v1 = acc[mi][ni][1] + b1;
            const float v2 = acc[mi][ni][2] + b0, v3 = acc[mi][ni][3] + b1;
            if (zmode == 0) {
                __nv_bfloat16* ob = (blockIdx.z == 0) ? g_q : g_k;
                const int bb1 = r1 >> 11, s1 = r1 & 2047;
                const int bb2 = r2 >> 11, s2 = r2 & 2047;
                const int h = col >> 6, d = col & 63;
                *(uint32_t*)(ob + (((size_t)(bb1 * HH + h)) * SS + s1) * HDD + d) = pack_bf16(v0, v1);
                *(uint32_t*)(ob + (((size_t)(bb2 * HH + h)) * SS + s2) * HDD + d) = pack_bf16(v2, v3);
            } else if (zmode == 2) {
                __nv_bfloat16* ov = (__nv_bfloat16*)g_v;
                const int bb1 = r1 >> 11, s1 = r1 & 2047;
                const int bb2 = r2 >> 11, s2 = r2 & 2047;
                const int h = (col & 1023) >> 6, d = col & 63;
                ov[(((size_t)(bb1 * HH + h) * (SS / 2) + (s1 >> 1)) * HDD + d)     * 2 + (s1 & 1)] = __float2bfloat16(v0);
                ov[(((size_t)(bb1 * HH + h) * (SS / 2) + (s1 >> 1)) * HDD + d + 1) * 2 + (s1 & 1)] = __float2bfloat16(v1);
                ov[(((size_t)(bb2 * HH + h) * (SS / 2) + (s2 >> 1)) * HDD + d)     * 2 + (s2 & 1)] = __float2bfloat16(v2);
                ov[(((size_t)(bb2 * HH + h) * (SS / 2) + (s2 >> 1)) * HDD + d + 1) * 2 + (s2 & 1)] = __float2bfloat16(v3);
            } else {
                const float2 rr1 = *(const float2*)(resid + (size_t)r1 * DD + col);
                const float2 rr2 = *(const float2*)(resid + (size_t)r2 * DD + col);
                *(float2*)(out + (size_t)r1 * DD + col) = make_float2(v0 + rr1.x, v1 + rr1.y);
                *(float2*)(out + (size_t)r2 * DD + col) = make_float2(v2 + rr2.x, v3 + rr2.y);
            }
        }
    }
}

// =================================================================
// Flash attention, bf16 m16n8k16, ex2.bf16x2 softmax + ones-MMA l.
// 2-stage K/V/mask pipeline (37.4 KB -> 5-6 CTAs/SM). Q staged
// through K buffer 0 before the pipeline starts. K frags via
// ldmatrix.x4 (measured best); V scalar word loads.
// Block = 64 q-rows of one (b,h), 128 thr (4 warps x 16 rows).
// =================================================================
#define QPW 36     // K word pitch (144 B rows)
#define VPW 72     // V word pitch (288 B rows)
#define KBUF (64 * QPW)       // 2304 words per K buffer (9216 B)
#define VBUF (32 * VPW)       // 2304 words per V buffer (9216 B)
#define K2E 0.1803368824f     // 0.125 * log2(e)
#define L2E 1.4426950409f
#define ONES2 0x3F803F80u     // bf16 {1.0, 1.0}
#define FLASH_SMEM ((2 * KBUF + 2 * VBUF) * 4 + 2 * 64 * 4)   // 37376 B

__global__ void __launch_bounds__(128) flash_bf16(const float* __restrict__ mask)
{
    extern __shared__ char smraw[];
    const uint32_t sbase = smem_u32(smraw);
    uint32_t* Ks = (uint32_t*)smraw;            // [2][64][QPW]
    uint32_t* Qs = Ks;                          // staged in K buffer 0
    uint32_t* Vs = Ks + 2 * KBUF;               // [2][32][VPW]
    float*    Ms = (float*)(Vs + 2 * VBUF);     // [2][64]

    const int tid  = threadIdx.x;
    const int warp = tid >> 5, lane = tid & 31;
    const int g = lane >> 2, c = lane & 3;
    const int wr = warp * 16;

    const int bh = blockIdx.y;
    const int b = bh >> 4;
    const int q0 = blockIdx.x * 64;

    const __nv_bfloat16* Qg = g_q + (size_t)bh * SS * HDD;
    const __nv_bfloat16* Kg = g_k + (size_t)bh * SS * HDD;
    const uint32_t*      Vg = g_v + (size_t)bh * (SS / 2) * HDD;
    const float* mrow = mask + (size_t)b * SS;

    // K ldmatrix lane offset (R14 measured-best path)
    const uint32_t off_k = (uint32_t)(((lane >> 4) * 8 + (lane & 7)) * 144
                                      + ((lane >> 3) & 1) * 16);

    // ---- prologue: Q -> K buffer 0 -> register frags ----
#pragma unroll
    for (int i = 0; i < 4; i++) {
        int idx = tid + 128 * i;
        int r = idx >> 3, kc = (idx & 7) * 8;
        cpa16(smem_u32((__nv_bfloat16*)Qs + r * 72 + kc),
              Qg + (size_t)(q0 + r) * HDD + kc);
    }
    CP_COMMIT; CP_WAIT0;
    __syncthreads();

    uint32_t qf[4][4];
#pragma unroll
    for (int ks = 0; ks < 4; ks++) {
        const int base = (wr + g) * QPW + ks * 8 + c;
        qf[ks][0] = Qs[base];
        qf[ks][1] = Qs[base + 8 * QPW];
        qf[ks][2] = Qs[base + 4];
        qf[ks][3] = Qs[base + 8 * QPW + 4];
    }
    __syncthreads();    // all warps have Q; buffer 0 may be refilled

#define LOAD_KV(k0v, bufv)                                                     \
    {                                                                          \
        const int _k0 = (k0v), _b = (bufv);                                    \
        _Pragma("unroll")                                                      \
        for (int i = 0; i < 4; i++) {                                          \
            int idx = tid + 128 * i;                                           \
            int r = idx >> 3, kc = (idx & 7) * 8;                              \
            cpa16(smem_u32((__nv_bfloat16*)(Ks + _b * KBUF) + r * 72 + kc),    \
                  Kg + (size_t)(_k0 + r) * HDD + kc);                          \
        }                                                                      \
        _Pragma("unroll")                                                      \
        for (int i = 0; i < 4; i++) {                                          \
            int idx = tid + 128 * i;                                           \
            int r = idx >> 4, cc = (idx & 15) * 4;                             \
            cpa16(smem_u32(Vs + _b * VBUF + r * VPW + cc),                     \
                  Vg + (size_t)(_k0 / 2 + r) * HDD + cc);                      \
        }                                                                      \
        if (tid < 16) cpa16(smem_u32(Ms + _b * 64 + tid * 4),                  \
                            mrow + _k0 + tid * 4);                             \
    }

    LOAD_KV(0, 0); CP_COMMIT;
    LOAD_KV(64, 1); CP_COMMIT;

    float l_acc[4] = {0.f, 0.f, 0.f, 0.f};
    const uint32_t ones[2] = {ONES2, ONES2};
    float o[8][4];
#pragma unroll
    for (int ni = 0; ni < 8; ni++)
#pragma unroll
        for (int r = 0; r < 4; r++) o[ni][r] = 0.f;

    const int NKT = SS / 64;
    for (int kt = 0; kt < NKT; kt++) {
        const int buf = kt & 1;
        if (kt < NKT - 1) { CP_WAIT1; } else { CP_WAIT0; }
        __syncthreads();

        const uint32_t Ku = sbase + buf * (KBUF * 4) + off_k;
        const uint32_t* Vb = Vs + buf * VBUF;
        const float* Mb = Ms + buf * 64;

        // ---- S = Q K^T (K frags via ldmatrix.x4) ----
        float s[8][4];
#pragma unroll
        for (int ni = 0; ni < 8; ni++)
#pragma unroll
            for (int r = 0; r < 4; r++) s[ni][r] = 0.f;

#pragma unroll
        for (int ks = 0; ks < 4; ks++) {
            uint32_t kf[4][4];
#pragma unroll
            for (int nig = 0; nig < 4; nig++)
                LDSM_X4(kf[nig][0], kf[nig][1], kf[nig][2], kf[nig][3],
                        Ku + nig * 2304 + ks * 32);
#pragma unroll
            for (int nig = 0; nig < 4; nig++) {
                mma_bf16(s[2 * nig],     qf[ks], &kf[nig][0]);
                mma_bf16(s[2 * nig + 1], qf[ks], &kf[nig][2]);
            }
        }

        // ---- t = s*K2E + mask*L2E (exp2 domain, no max) ----
#pragma unroll
        for (int ni = 0; ni < 8; ni++) {
            const int col = ni * 8 + 2 * c;
            const float mk0 = Mb[col] * L2E, mk1 = Mb[col + 1] * L2E;
            s[ni][0] = fmaf(s[ni][0], K2E, mk0);
            s[ni][1] = fmaf(s[ni][1], K2E, mk1);
            s[ni][2] = fmaf(s[ni][2], K2E, mk0);
            s[ni][3] = fmaf(s[ni][3], K2E, mk1);
        }

        // ---- O += P V ; l += P*1  (P via ex2.bf16x2, in regs) ----
#pragma unroll
        for (int ks = 0; ks < 4; ks++) {
            uint32_t pf[4];
            pf[0] = exp2_bf16x2(s[2 * ks][1],     s[2 * ks][0]);
            pf[1] = exp2_bf16x2(s[2 * ks][3],     s[2 * ks][2]);
            pf[2] = exp2_bf16x2(s[2 * ks + 1][1], s[2 * ks + 1][0]);
            pf[3] = exp2_bf16x2(s[2 * ks + 1][3], s[2 * ks + 1][2]);
            mma_bf16(l_acc, pf, ones);
#pragma unroll
            for (int ni = 0; ni < 8; ni++) {
                uint32_t bfr[2];
                const int vb = (ks * 8 + c) * VPW + ni * 8 + g;
                bfr[0] = Vb[vb];
                bfr[1] = Vb[vb + 4 * VPW];
                mma_bf16(o[ni], pf, bfr);
            }
        }
        __syncthreads();   // all warps done with buf before refill
        if (kt + 2 < NKT) { LOAD_KV((kt + 2) * 64, buf); CP_COMMIT; }
    }
#undef LOAD_KV

    // ---- normalize (l replicated across columns by ones-MMA) ----
    const float inv0 = 1.f / l_acc[0];
    const float inv1 = 1.f / l_acc[2];
    const int h = bh & 15;
    __nv_bfloat16* Cg = g_ctx + (size_t)(b * SS + q0) * DD + h * HDD;
#pragma unroll
    for (int ni = 0; ni < 8; ni++) {
        const int col = ni * 8 + 2 * c;
        *(uint32_t*)(Cg + (size_t)(wr + g) * DD + col)     = pack_bf16(o[ni][0] * inv0, o[ni][1] * inv0);
        *(uint32_t*)(Cg + (size_t)(wr + g + 8) * DD + col) = pack_bf16(o[ni][2] * inv1, o[ni][3] * inv1);
    }
}

// =================================================================
// LayerNorm
// =================================================================
__device__ __forceinline__ float blockSum(float v, float* red)
{
    const int lane = threadIdx.x & 31, wid = threadIdx.x >> 5;
#pragma unroll
    for (int o = 16; o > 0; o >>= 1) v += __shfl_xor_sync(0xffffffffu, v, o);
    if (lane == 0) red[wid] = v;
    __syncthreads();
    if (wid == 0) {
        float t = (lane < 8) ? red[lane] : 0.f;
#pragma unroll
        for (int o = 4; o > 0; o >>= 1) t += __shfl_xor_sync(0xffffffffu, t, o);
        if (lane == 0) red[0] = t;
    }
    __syncthreads();
    float r = red[0];
    __syncthreads();
    return r;
}

__global__ void __launch_bounds__(256) ln_kernel(
    const float* __restrict__ x, const float* __restrict__ gamma,
    const float* __restrict__ beta, float* __restrict__ out)
{
    __shared__ float red[8];
    const int row = blockIdx.x;
    const int t = threadIdx.x;

    float4 v = ((const float4*)(x + (size_t)row * DD))[t];
    float s = v.x + v.y + v.z + v.w;
    float mu = blockSum(s, red) * (1.0f / DD);

    float dx0 = v.x - mu, dx1 = v.y - mu, dx2 = v.z - mu, dx3 = v.w - mu;
    float sq = dx0 * dx0 + dx1 * dx1 + dx2 * dx2 + dx3 * dx3;
    float var = blockSum(sq, red) * (1.0f / DD);
    float inv = rsqrtf(var + 1e-12f);

    float4 g = ((const float4*)gamma)[t];
    float4 b = ((const float4*)beta)[t];
    float4 o;
    o.x = dx0 * inv * g.x + b.x;
    o.y = dx1 * inv * g.y + b.y;
    o.z = dx2 * inv * g.z + b.z;
    o.w = dx3 * inv * g.w + b.w;
    ((float4*)(out + (size_t)row * DD))[t] = o;
}

// =================================================================
extern "C" void kernel_launch(void* const* d_in, const int* in_sizes, int n_in,
                              void* d_out, int out_size)
{
    const float* hidden = (const float*)d_in[0];
    const float* mask   = (const float*)d_in[1];
    const float* Wq     = (const float*)d_in[2];
    const float* bq     = (const float*)d_in[3];
    const float* Wk     = (const float*)d_in[4];
    const float* bk     = (const float*)d_in[5];
    const float* Wv     = (const float*)d_in[6];
    const float* bv     = (const float*)d_in[7];
    const float* Wo     = (const float*)d_in[8];
    const float* bo     = (const float*)d_in[9];
    const float* gamma  = (const float*)d_in[10];
    const float* beta   = (const float*)d_in[11];
    float* out = (float*)d_out;

    __nv_bfloat16 *hb, *ctx;
    uint32_t *wo;
    float *x;
    cudaGetSymbolAddress((void**)&hb,  g_hb);
    cudaGetSymbolAddress((void**)&ctx, g_ctx);
    cudaGetSymbolAddress((void**)&x,   g_x);
    cudaGetSymbolAddress((void**)&wo,  g_wo);

    cudaFuncSetAttribute(gemm_bf16,
                         cudaFuncAttributeMaxDynamicSharedMemorySize, GEMM_SMEM);
    cudaFuncSetAttribute(flash_bf16,
                         cudaFuncAttributeMaxDynamicSharedMemorySize, FLASH_SMEM);

    // conversions
    conv_h<<<NT * DD / 4 / 256, 256>>>(hidden, hb);
    pack_all<<<2048, 256>>>(Wq, Wk, Wv, Wo);

    // fused QKV projections (z = 0:Q, 1:K, 2:V)
    gemm_bf16<<<dim3(DD / 128, NT / 128, 3), 256, GEMM_SMEM>>>(
        hb, nullptr, nullptr, bq, bk, bv, nullptr, nullptr, 3);

    flash_bf16<<<dim3(SS / 64, BB * HH), 128, FLASH_SMEM>>>(mask);

    gemm_bf16<<<dim3(DD / 128, NT / 128, 1), 256, GEMM_SMEM>>>(
        ctx, wo, bo, nullptr, nullptr, nullptr, hidden, x, 1);

    ln_kernel<<<NT, 256>>>(x, gamma, beta, out);
}